// round 12
// baseline (speedup 1.0000x reference)
#include <cuda_runtime.h>
#include <cuda_bf16.h>
#include <cstdint>

#define TT   1024
#define BSZ  64
#define DD   256
#define HH   256
#define G4   1024            // 4*H
#define TBH  (TT*BSZ*HH)
#define BH   (BSZ*HH)
#define NCTA 128             // 16 clusters x 8 CTAs
#define CLU  8
#define NTHR 1024

typedef unsigned long long ull;

// Scratch (device globals: no runtime allocation allowed)
__device__ float g_Z[(size_t)TT * BSZ * G4];   // [t][b][gate*256+u]  (256 MB)

#define FMA_F32X2(d, a, b, c) \
    asm("fma.rn.f32x2 %0, %1, %2, %3;" : "=l"(d) : "l"(a), "l"(b), "l"(c))
#define ADD_F32X2(d, a, b) \
    asm("add.rn.f32x2 %0, %1, %2;" : "=l"(d) : "l"(a), "l"(b))
#define UNPACK2(lo, hi, s) \
    asm("mov.b64 {%0, %1}, %2;" : "=f"(lo), "=f"(hi) : "l"(s))

// ---------------------------------------------------------------------------
// Phase 1: Z[t][b][g*256+u] = bias_g[u] + sum_k x[t][b][k] * W_g[u*512 + k]
// GEMM M=65536 (t*64+b), N=1024, K=256. BM=128, BN=128, BK=16, 8x8 tiles.
// (scalar-FFMA version - measured faster than the FFMA2 variant)
// ---------------------------------------------------------------------------
__global__ __launch_bounds__(256, 2)
void proj_kernel(const float* __restrict__ x,
                 const float* __restrict__ Wf, const float* __restrict__ bf,
                 const float* __restrict__ Wi, const float* __restrict__ bi,
                 const float* __restrict__ Wg, const float* __restrict__ bg,
                 const float* __restrict__ Wo, const float* __restrict__ bo)
{
    __shared__ float As[16 * 132];
    __shared__ float Bs[16 * 132];

    const int tid = threadIdx.x;
    const int tx  = tid & 15;
    const int ty  = tid >> 4;
    const int bm    = blockIdx.y * 128;
    const int gate  = blockIdx.x >> 1;
    const int ucol0 = (blockIdx.x & 1) * 128;

    const float* W    = (gate == 0) ? Wf : (gate == 1) ? Wi : (gate == 2) ? Wg : Wo;
    const float* bias = (gate == 0) ? bf : (gate == 1) ? bi : (gate == 2) ? bg : bo;

    float acc[8][8];
#pragma unroll
    for (int i = 0; i < 8; i++)
#pragma unroll
        for (int j = 0; j < 8; j++) acc[i][j] = 0.f;

    for (int k0 = 0; k0 < 256; k0 += 16) {
#pragma unroll
        for (int it = 0; it < 2; it++) {
            int f4  = tid + it * 256;
            int row = f4 >> 2;
            int kc  = (f4 & 3) << 2;
            float4 av = *(const float4*)(x + (size_t)(bm + row) * 256 + k0 + kc);
            As[(kc + 0) * 132 + row] = av.x;
            As[(kc + 1) * 132 + row] = av.y;
            As[(kc + 2) * 132 + row] = av.z;
            As[(kc + 3) * 132 + row] = av.w;
            float4 bv = *(const float4*)(W + (size_t)(ucol0 + row) * 512 + k0 + kc);
            Bs[(kc + 0) * 132 + row] = bv.x;
            Bs[(kc + 1) * 132 + row] = bv.y;
            Bs[(kc + 2) * 132 + row] = bv.z;
            Bs[(kc + 3) * 132 + row] = bv.w;
        }
        __syncthreads();
#pragma unroll
        for (int kk = 0; kk < 16; kk++) {
            float4 a0 = *(const float4*)&As[kk * 132 + ty * 8];
            float4 a1 = *(const float4*)&As[kk * 132 + ty * 8 + 4];
            float4 b0 = *(const float4*)&Bs[kk * 132 + tx * 8];
            float4 b1 = *(const float4*)&Bs[kk * 132 + tx * 8 + 4];
            float a[8] = {a0.x, a0.y, a0.z, a0.w, a1.x, a1.y, a1.z, a1.w};
            float b[8] = {b0.x, b0.y, b0.z, b0.w, b1.x, b1.y, b1.z, b1.w};
#pragma unroll
            for (int i = 0; i < 8; i++)
#pragma unroll
                for (int j = 0; j < 8; j++) acc[i][j] += a[i] * b[j];
        }
        __syncthreads();
    }

    float4 q0 = *(const float4*)(bias + ucol0 + tx * 8);
    float4 q1 = *(const float4*)(bias + ucol0 + tx * 8 + 4);
    float bb[8] = {q0.x, q0.y, q0.z, q0.w, q1.x, q1.y, q1.z, q1.w};

#pragma unroll
    for (int i = 0; i < 8; i++) {
        size_t m  = (size_t)(bm + ty * 8 + i);
        float* zp = g_Z + m * 1024 + gate * 256 + ucol0 + tx * 8;
        float4 v0 = {acc[i][0] + bb[0], acc[i][1] + bb[1], acc[i][2] + bb[2], acc[i][3] + bb[3]};
        float4 v1 = {acc[i][4] + bb[4], acc[i][5] + bb[5], acc[i][6] + bb[6], acc[i][7] + bb[7]};
        *(float4*)zp       = v0;
        *(float4*)(zp + 4) = v1;
    }
}

// ---------------------------------------------------------------------------
// Phase 2: cluster recurrence, SOFTWARE-PIPELINED over 2 batch groups.
// 16 clusters x 8 CTAs x 1024 threads. Cluster cid owns batches [4cid,4cid+4),
// split into group 0 = {4cid,4cid+1}, group 1 = {4cid+2,4cid+3}. Batches are
// independent chains, so group g's DSMEM push + barrier propagation overlaps
// group g^1's compute (a full phase of latency cover).
// Per-group mbarrier (count=8): all threads acquire-wait; pushes ->
// __syncthreads -> tid0 release-arrives on all 8 CTAs.
// ---------------------------------------------------------------------------
__device__ __forceinline__ float sig_(float v)  { return __fdividef(1.f, 1.f + __expf(-v)); }
__device__ __forceinline__ float tanh_(float v) { return __fdividef(2.f, 1.f + __expf(-2.f * v)) - 1.f; }

__device__ __forceinline__ uint32_t smem_u32(const void* p) {
    uint32_t a;
    asm("{ .reg .u64 t; cvta.to.shared.u64 t, %1; cvt.u32.u64 %0, t; }"
        : "=r"(a) : "l"(p));
    return a;
}

__device__ __forceinline__ void push_h(uint32_t laddr, int rank, float v) {
    uint32_t ra;
    asm("mapa.shared::cluster.u32 %0, %1, %2;" : "=r"(ra) : "r"(laddr), "r"(rank));
    asm volatile("st.shared::cluster.f32 [%0], %1;" :: "r"(ra), "f"(v));
}

__device__ __forceinline__ void remote_arrive(uint32_t bar_laddr, int rank) {
    asm volatile(
        "{ .reg .b32 ra;\n\t"
        "mapa.shared::cluster.u32 ra, %0, %1;\n\t"
        "mbarrier.arrive.release.cluster.shared::cluster.b64 _, [ra]; }"
        :: "r"(bar_laddr), "r"(rank) : "memory");
}

__device__ __forceinline__ void bar_wait(uint32_t bar_laddr, unsigned parity) {
    asm volatile(
        "{ .reg .pred P;\n\t"
        "W_%=:\n\t"
        "mbarrier.try_wait.parity.acquire.cluster.shared::cta.b64 P, [%0], %1, 0x989680;\n\t"
        "@!P bra W_%=;\n\t"
        "}"
        :: "r"(bar_laddr), "r"(parity) : "memory");
}

#define CLUSTER_SYNC_() do { \
    asm volatile("barrier.cluster.arrive.aligned;" ::: "memory"); \
    asm volatile("barrier.cluster.wait.aligned;"   ::: "memory"); \
} while (0)

__global__ __launch_bounds__(NTHR, 1)
void lstm_kernel(const float* __restrict__ Wf, const float* __restrict__ Wi,
                 const float* __restrict__ Wg, const float* __restrict__ Wo,
                 float* __restrict__ out)
{
    __shared__ float hs[2][2][2][256];   // [group][buf][bq][k]  (8KB)
    __shared__ float pre4[2][8][128];    // [bq][kq][col]        (4KB)
    __shared__ ull   mbar[2];            // per-group barriers

    const int tid  = threadIdx.x;
    const int lane = tid & 31;
    const int w    = tid >> 5;
    const int kq   = w >> 2;            // k-range [32kq, 32kq+32)
    const int cg   = w & 3;
    const int lc   = cg * 32 + lane;    // local col 0..127

    uint32_t rank;
    asm("mov.u32 %0, %%cluster_ctarank;" : "=r"(rank));
    const int cid = blockIdx.x >> 3;
    const int b0  = cid * 4;
    const uint32_t mb0 = smem_u32(&mbar[0]);
    const uint32_t mb1 = smem_u32(&mbar[1]);

    // ---- recurrent weights: this thread's col, k in [32kq, 32kq+32) ----
    const int uu = lc >> 2;
    const int gt = lc & 3;
    const float* Ws[4] = {Wf, Wi, Wg, Wo};
    const ull* wrow = (const ull*)(Ws[gt] + (size_t)(rank * 32 + uu) * 512 + 256 + kq * 32);
    ull wk[16];
#pragma unroll
    for (int j = 0; j < 16; j++) wk[j] = wrow[j];

    // zero h buffers; init per-group mbarriers (8 arrivals each)
    for (int i = tid; i < 2 * 2 * 2 * 256; i += NTHR) ((float*)hs)[i] = 0.f;
    if (tid == 0) {
        asm volatile("mbarrier.init.shared.b64 [%0], %1;" :: "r"(mb0), "r"(CLU) : "memory");
        asm volatile("mbarrier.init.shared.b64 [%0], %1;" :: "r"(mb1), "r"(CLU) : "memory");
    }
    __syncthreads();

    // epilogue identity (threads 0..63): bq = tid>>5 (0..1), uue = tid&31
    const int bq_e  = tid >> 5;
    const int uu_e  = tid & 31;
    const int ug_e  = (int)rank * 32 + uu_e;
    // group-dependent batch: bgA = b0+bq_e, bgB = b0+2+bq_e
    const int bgA = b0 + bq_e;
    const int bgB = b0 + 2 + bq_e;
    const float* zbaseA = g_Z + (size_t)bgA * 1024 + ug_e;
    const float* zbaseB = g_Z + (size_t)bgB * 1024 + ug_e;
    // hs element addr for [0][0][bq_e][ug_e]; group/buf offsets are +2KB each
    const uint32_t hbase = smem_u32(&hs[0][0][bq_e][ug_e]);
    float cstA = 0.f, cstB = 0.f;

    CLUSTER_SYNC_();   // hs zeros + mbarrier init visible cluster-wide

#define PHASE(G, ZBASE, CST, MB)                                              \
    do {                                                                      \
        float z0 = 0.f, z1 = 0.f, z2 = 0.f, z3 = 0.f;                         \
        if (tid < 64) {                                                       \
            const float* zr = (ZBASE) + (size_t)t * 65536;                    \
            z0 = __ldcs(zr);       z1 = __ldcs(zr + 256);                     \
            z2 = __ldcs(zr + 512); z3 = __ldcs(zr + 768);                     \
        }                                                                     \
        if (t > 0) bar_wait((MB), (unsigned)((t - 1) & 1));                   \
        const int buf = t & 1;                                                \
        _Pragma("unroll")                                                     \
        for (int bq = 0; bq < 2; bq++) {                                      \
            const ulonglong2* hp2 =                                           \
                (const ulonglong2*)&hs[G][buf][bq][kq * 32];                  \
            ull a0 = 0ull, a1 = 0ull;                                         \
            _Pragma("unroll")                                                 \
            for (int j = 0; j < 8; j++) {                                     \
                ulonglong2 hv = hp2[j];                                       \
                FMA_F32X2(a0, wk[2 * j + 0], hv.x, a0);                       \
                FMA_F32X2(a1, wk[2 * j + 1], hv.y, a1);                       \
            }                                                                 \
            ADD_F32X2(a0, a0, a1);                                            \
            float lo, hi;                                                     \
            UNPACK2(lo, hi, a0);                                              \
            pre4[bq][kq][lc] = lo + hi;                                       \
        }                                                                     \
        __syncthreads();                                                      \
        float h = 0.f;                                                        \
        if (tid < 64) {                                                       \
            float pf = 0.f, pi = 0.f, pg = 0.f, po = 0.f;                     \
            _Pragma("unroll")                                                 \
            for (int q = 0; q < 8; q++) {                                     \
                float4 s = *(const float4*)&pre4[bq_e][q][uu_e * 4];          \
                pf += s.x; pi += s.y; pg += s.z; po += s.w;                   \
            }                                                                 \
            float fg = sig_ (pf + z0);                                        \
            float ig = sig_ (pi + z1);                                        \
            float gg = tanh_(pg + z2);                                        \
            float og = sig_ (po + z3);                                        \
            (CST) = fg * (CST) + ig * gg;                                     \
            h = og * tanh_((CST));                                            \
            uint32_t ha = hbase + (uint32_t)(((G) * 2 + (buf ^ 1)) * 2048);   \
            _Pragma("unroll")                                                 \
            for (int r = 0; r < CLU; r++) push_h(ha, r, h);                   \
        }                                                                     \
        __syncthreads();                                                      \
        if (tid == 0) {                                                       \
            _Pragma("unroll")                                                 \
            for (int r = 0; r < CLU; r++) remote_arrive((MB), r);             \
        }                                                                     \
        if (tid < 64) {                                                       \
            const int bg_ = ((G) == 0) ? bgA : bgB;                           \
            out[((size_t)t * 64 + bg_) * 256 + ug_e] = h;                     \
            if (t == TT - 1) {                                                \
                out[TBH + bg_ * 256 + ug_e]      = h;                         \
                out[TBH + BH + bg_ * 256 + ug_e] = (CST);                     \
            }                                                                 \
        }                                                                     \
    } while (0)

    for (int t = 0; t < TT; t++) {
        PHASE(0, zbaseA, cstA, mb0);
        PHASE(1, zbaseB, cstB, mb1);
    }
#undef PHASE

    // no CTA exits while peers may still push/arrive into its SMEM
    CLUSTER_SYNC_();
}

// ---------------------------------------------------------------------------
// Launch
// ---------------------------------------------------------------------------
extern "C" void kernel_launch(void* const* d_in, const int* in_sizes, int n_in,
                              void* d_out, int out_size)
{
    const float* x  = (const float*)d_in[0];
    const float* Wf = (const float*)d_in[1];
    const float* bf = (const float*)d_in[2];
    const float* Wi = (const float*)d_in[3];
    const float* bi = (const float*)d_in[4];
    const float* Wg = (const float*)d_in[5];
    const float* bg = (const float*)d_in[6];
    const float* Wo = (const float*)d_in[7];
    const float* bo = (const float*)d_in[8];
    float* out = (float*)d_out;

    proj_kernel<<<dim3(8, 512), 256>>>(x, Wf, bf, Wi, bi, Wg, bg, Wo, bo);

    cudaLaunchConfig_t cfg = {};
    cfg.gridDim  = dim3(NCTA, 1, 1);
    cfg.blockDim = dim3(NTHR, 1, 1);
    cfg.dynamicSmemBytes = 0;
    cudaLaunchAttribute attrs[1];
    attrs[0].id = cudaLaunchAttributeClusterDimension;
    attrs[0].val.clusterDim.x = CLU;
    attrs[0].val.clusterDim.y = 1;
    attrs[0].val.clusterDim.z = 1;
    cfg.attrs = attrs;
    cfg.numAttrs = 1;
    cudaLaunchKernelEx(&cfg, lstm_kernel, Wf, Wi, Wg, Wo, out);
}

// round 14
// speedup vs baseline: 1.3423x; 1.3423x over previous
#include <cuda_runtime.h>
#include <cstdint>

#define TT   1024
#define BSZ  64
#define TBH  (TT*BSZ*256)
#define BH   (BSZ*256)
#define NCTA 128             // 16 clusters x 8 CTAs
#define CLU  8
#define NTHR 512

typedef unsigned long long ull;

#define FMA_F32X2(d, a, b, c) \
    asm("fma.rn.f32x2 %0, %1, %2, %3;" : "=l"(d) : "l"(a), "l"(b), "l"(c))
#define ADD_F32X2(d, a, b) \
    asm("add.rn.f32x2 %0, %1, %2;" : "=l"(d) : "l"(a), "l"(b))
#define UNPACK2(lo, hi, s) \
    asm("mov.b64 {%0, %1}, %2;" : "=f"(lo), "=f"(hi) : "l"(s))

// ---- dynamic SMEM layout (float offsets) ----
#define WX_STRIDE 260                        // 1040B rows: conflict-free LDS.128
#define WX_OFF   0                           // wx [128][260]      = 33280
#define HS_OFF   (128 * WX_STRIDE)           // hs [2][4][256]     = 2048
#define PRE_OFF  (HS_OFF + 2048)             // pre4 [4][4][128]   = 2048
#define ZPRE_OFF (PRE_OFF + 2048)            // zpre [4][4][128]   = 2048
#define XS_OFF   (ZPRE_OFF + 2048)           // xs [4][256]        = 1024
#define ZS_OFF   (XS_OFF + 1024)             // zs [2][4][128]     = 1024
#define SM_TOT   (ZS_OFF + 1024)             // 41472 floats = 165888 B

__device__ __forceinline__ float sig_(float v)  { return __fdividef(1.f, 1.f + __expf(-v)); }
__device__ __forceinline__ float tanh_(float v) { return __fdividef(2.f, 1.f + __expf(-2.f * v)) - 1.f; }

__device__ __forceinline__ uint32_t smem_u32(const void* p) {
    uint32_t a;
    asm("{ .reg .u64 t; cvta.to.shared.u64 t, %1; cvt.u32.u64 %0, t; }"
        : "=r"(a) : "l"(p));
    return a;
}

__device__ __forceinline__ void push_h(uint32_t laddr, int rank, float v) {
    uint32_t ra;
    asm("mapa.shared::cluster.u32 %0, %1, %2;" : "=r"(ra) : "r"(laddr), "r"(rank));
    asm volatile("st.shared::cluster.f32 [%0], %1;" :: "r"(ra), "f"(v));
}

#define CLUSTER_SYNC_() do { \
    asm volatile("barrier.cluster.arrive.aligned;" ::: "memory"); \
    asm volatile("barrier.cluster.wait.aligned;"   ::: "memory"); \
} while (0)

#define XBAR_() asm volatile("bar.sync 1, 384;" ::: "memory")

// ---------------------------------------------------------------------------
// Fused kernel: 16 clusters x 8 CTAs x 512 threads. Cluster cid owns batches
// [4cid, 4cid+4); CTA rank r owns hidden units [32r,32r+32) = 128 gate cols.
// Per step t:
//   all warps : recurrent GEMM (h from SMEM, weights in regs) -> pre4
//   sync
//   warps 0-3 : epilogue (pre4 + zs[t&1]) -> c,h; DSMEM pushes to 8 CTAs
//   warps 4-15: STS x(t+1) -> xs (256 float4, ONE per thread); bar;
//               x-GEMM (Wx in SMEM) -> zpre; bar;
//               warps 4-7: reduce zpre + bias -> zs[(t+1)&1]
//   cluster arrive+wait
// The input projection is computed one step ahead inside the idle issue
// slots of the recurrence. No g_Z, single kernel.
// ---------------------------------------------------------------------------
__global__ __launch_bounds__(NTHR, 1)
void lstm_fused(const float* __restrict__ x,
                const float* __restrict__ Wf, const float* __restrict__ bf,
                const float* __restrict__ Wi, const float* __restrict__ bi,
                const float* __restrict__ Wg, const float* __restrict__ bg,
                const float* __restrict__ Wo, const float* __restrict__ bo,
                float* __restrict__ out)
{
    extern __shared__ float sm[];
    float* wx   = sm + WX_OFF;
    float* hs   = sm + HS_OFF;
    float* pre4 = sm + PRE_OFF;
    float* zpre = sm + ZPRE_OFF;
    float* xs   = sm + XS_OFF;
    float* zs   = sm + ZS_OFF;

    const int tid  = threadIdx.x;
    const int lane = tid & 31;
    const int w    = tid >> 5;
    const int kq   = w >> 2;            // k-range [64kq, 64kq+64)
    const int cg   = w & 3;
    const int lc   = cg * 32 + lane;    // local col 0..127

    uint32_t rank;
    asm("mov.u32 %0, %%cluster_ctarank;" : "=r"(rank));
    const int cid = blockIdx.x >> 3;
    const int b0  = cid * 4;

    const float* Ws[4] = {Wf, Wi, Wg, Wo};

    // ---- recurrent weights in regs: col lc, k in [64kq, 64kq+64) ----
    const int uu = lc >> 2;
    const int gt = lc & 3;
    const ull* wrow = (const ull*)(Ws[gt] + (size_t)(rank * 32 + uu) * 512 + 256 + kq * 64);
    ull wk[32];
#pragma unroll
    for (int j = 0; j < 32; j++) wk[j] = wrow[j];

    // ---- zero hs; load Wx (x-part rows of this CTA's 128 cols) ----
    for (int i = tid; i < 2 * 4 * 256; i += NTHR) hs[i] = 0.f;
#pragma unroll
    for (int i = 0; i < 16; i++) {
        int f4  = tid + NTHR * i;          // 8192 float4
        int row = f4 >> 6;
        int k4  = f4 & 63;
        float4 v = *(const float4*)(Ws[row & 3] +
                     (size_t)(rank * 32 + (row >> 2)) * 512 + k4 * 4);
        *(float4*)&wx[row * WX_STRIDE + k4 * 4] = v;
    }

    // identities
    const int xtid = tid - 128;                  // valid for tid>=128
    const int bq_e = tid >> 5;                   // epilogue (tid<128)
    const int uu_e = tid & 31;
    const int bg_e = b0 + bq_e;
    const int ug_e = (int)rank * 32 + uu_e;
    const uint32_t haddr0 = smem_u32(&hs[(0 * 4 + bq_e) * 256 + ug_e]);
    const uint32_t haddr1 = smem_u32(&hs[(1 * 4 + bq_e) * 256 + ug_e]);
    float cstate = 0.f;

    // bias for z-reduce threads (xtid<128): col = xtid
    float biasv = 0.f;
    if (tid >= 128 && xtid < 128) {
        const float* Bs_[4] = {bf, bi, bg, bo};
        biasv = Bs_[xtid & 3][rank * 32 + (xtid >> 2)];
    }

    // ---- prologue: compute z(0) -> zs[0] ----
    // x slice for 4 batches = 1024 floats = 256 float4; ONE float4 per thread.
    float4 xr0;
    if (tid >= 128 && xtid < 256) {
        const float4* xsrc = (const float4*)(x + (size_t)b0 * 256);
        xr0 = xsrc[xtid];
    }
    __syncthreads();   // wx ready before x-GEMM below
    if (tid >= 128 && xtid < 256) {
        *(float4*)&xs[xtid * 4] = xr0;
    }
    __syncthreads();
    if (tid >= 128) {
#pragma unroll
        for (int un = 0; un < 2; un++) {
            int ucol, ukq;
            if (un == 0) { ucol = xtid & 127; ukq = xtid >> 7; }   // ukq 0..2
            else         { ucol = xtid;       ukq = 3; }
            if (un == 1 && xtid >= 128) break;
            const ulonglong2* wv = (const ulonglong2*)&wx[ucol * WX_STRIDE + ukq * 64];
            ulonglong2 wr[16];
#pragma unroll
            for (int j = 0; j < 16; j++) wr[j] = wv[j];
#pragma unroll
            for (int bq = 0; bq < 4; bq++) {
                const ulonglong2* xv = (const ulonglong2*)&xs[bq * 256 + ukq * 64];
                ull a0 = 0ull, a1 = 0ull;
#pragma unroll
                for (int j = 0; j < 16; j++) {
                    ulonglong2 xp = xv[j];
                    FMA_F32X2(a0, wr[j].x, xp.x, a0);
                    FMA_F32X2(a1, wr[j].y, xp.y, a1);
                }
                ADD_F32X2(a0, a0, a1);
                float lo, hi; UNPACK2(lo, hi, a0);
                zpre[(bq * 4 + ukq) * 128 + ucol] = lo + hi;
            }
        }
    }
    __syncthreads();
    if (tid >= 128 && xtid < 128) {
#pragma unroll
        for (int bq = 0; bq < 4; bq++) {
            zs[(0 * 4 + bq) * 128 + xtid] = biasv
                + zpre[(bq * 4 + 0) * 128 + xtid] + zpre[(bq * 4 + 1) * 128 + xtid]
                + zpre[(bq * 4 + 2) * 128 + xtid] + zpre[(bq * 4 + 3) * 128 + xtid];
        }
    }
    CLUSTER_SYNC_();   // hs zeros visible cluster-wide

    // ---- main loop ----
    for (int t = 0; t < TT; t++) {
        const int t1 = (t + 1 < TT) ? (t + 1) : t;

        // x(t+1) prefetch to regs (ONE float4 per thread, 256 total)
        if (tid >= 128 && xtid < 256) {
            const float4* xsrc = (const float4*)(x + ((size_t)t1 * 64 + b0) * 256);
            xr0 = xsrc[xtid];
        }

        // ---- recurrent GEMM: 4 batches, this thread's col, 64 k's ----
        const int buf = t & 1;
#pragma unroll
        for (int bq = 0; bq < 4; bq++) {
            const ulonglong2* hp2 = (const ulonglong2*)&hs[(buf * 4 + bq) * 256 + kq * 64];
            ull a0 = 0ull, a1 = 0ull;
#pragma unroll
            for (int j = 0; j < 16; j++) {
                ulonglong2 hv = hp2[j];
                FMA_F32X2(a0, wk[2 * j + 0], hv.x, a0);
                FMA_F32X2(a1, wk[2 * j + 1], hv.y, a1);
            }
            ADD_F32X2(a0, a0, a1);
            float lo, hi; UNPACK2(lo, hi, a0);
            pre4[(bq * 4 + kq) * 128 + lc] = lo + hi;
        }
        __syncthreads();

        if (tid < 128) {
            // ---- h epilogue: one (batch, unit) per thread ----
            float pf = 0.f, pi = 0.f, pg = 0.f, po = 0.f;
#pragma unroll
            for (int q = 0; q < 4; q++) {
                float4 s = *(const float4*)&pre4[(bq_e * 4 + q) * 128 + uu_e * 4];
                pf += s.x; pi += s.y; pg += s.z; po += s.w;
            }
            float4 zv = *(const float4*)&zs[((t & 1) * 4 + bq_e) * 128 + uu_e * 4];
            float fg = sig_ (pf + zv.x);
            float ig = sig_ (pi + zv.y);
            float gg = tanh_(pg + zv.z);
            float og = sig_ (po + zv.w);
            cstate = fg * cstate + ig * gg;
            float h = og * tanh_(cstate);

            uint32_t ha = (buf ? haddr0 : haddr1);
#pragma unroll
            for (int r = 0; r < CLU; r++) push_h(ha, r, h);

            out[((size_t)t * 64 + bg_e) * 256 + ug_e] = h;
            if (t == TT - 1) {
                out[TBH + bg_e * 256 + ug_e]      = h;
                out[TBH + BH + bg_e * 256 + ug_e] = cstate;
            }
        } else {
            // ---- x machinery (warps 4-15): produce zs[(t+1)&1] ----
            if (xtid < 256) {
                *(float4*)&xs[xtid * 4] = xr0;
            }
            XBAR_();
#pragma unroll
            for (int un = 0; un < 2; un++) {
                int ucol, ukq;
                if (un == 0) { ucol = xtid & 127; ukq = xtid >> 7; }
                else         { ucol = xtid;       ukq = 3; }
                if (un == 1 && xtid >= 128) break;
                const ulonglong2* wv = (const ulonglong2*)&wx[ucol * WX_STRIDE + ukq * 64];
                ulonglong2 wr[16];
#pragma unroll
                for (int j = 0; j < 16; j++) wr[j] = wv[j];
#pragma unroll
                for (int bq = 0; bq < 4; bq++) {
                    const ulonglong2* xv = (const ulonglong2*)&xs[bq * 256 + ukq * 64];
                    ull a0 = 0ull, a1 = 0ull;
#pragma unroll
                    for (int j = 0; j < 16; j++) {
                        ulonglong2 xp = xv[j];
                        FMA_F32X2(a0, wr[j].x, xp.x, a0);
                        FMA_F32X2(a1, wr[j].y, xp.y, a1);
                    }
                    ADD_F32X2(a0, a0, a1);
                    float lo, hi; UNPACK2(lo, hi, a0);
                    zpre[(bq * 4 + ukq) * 128 + ucol] = lo + hi;
                }
            }
            XBAR_();
            if (xtid < 128) {
                const int zslot = (t + 1) & 1;
#pragma unroll
                for (int bq = 0; bq < 4; bq++) {
                    zs[(zslot * 4 + bq) * 128 + xtid] = biasv
                        + zpre[(bq * 4 + 0) * 128 + xtid] + zpre[(bq * 4 + 1) * 128 + xtid]
                        + zpre[(bq * 4 + 2) * 128 + xtid] + zpre[(bq * 4 + 3) * 128 + xtid];
                }
            }
        }

        CLUSTER_SYNC_();
    }
}

// ---------------------------------------------------------------------------
// Launch: single fused kernel.
// ---------------------------------------------------------------------------
extern "C" void kernel_launch(void* const* d_in, const int* in_sizes, int n_in,
                              void* d_out, int out_size)
{
    const float* x  = (const float*)d_in[0];
    const float* Wf = (const float*)d_in[1];
    const float* bf = (const float*)d_in[2];
    const float* Wi = (const float*)d_in[3];
    const float* bi = (const float*)d_in[4];
    const float* Wg = (const float*)d_in[5];
    const float* bg = (const float*)d_in[6];
    const float* Wo = (const float*)d_in[7];
    const float* bo = (const float*)d_in[8];
    float* out = (float*)d_out;

    static bool attr_set = false;
    if (!attr_set) {
        cudaFuncSetAttribute(lstm_fused,
                             cudaFuncAttributeMaxDynamicSharedMemorySize,
                             SM_TOT * (int)sizeof(float));
        attr_set = true;
    }

    cudaLaunchConfig_t cfg = {};
    cfg.gridDim  = dim3(NCTA, 1, 1);
    cfg.blockDim = dim3(NTHR, 1, 1);
    cfg.dynamicSmemBytes = SM_TOT * sizeof(float);
    cudaLaunchAttribute attrs[1];
    attrs[0].id = cudaLaunchAttributeClusterDimension;
    attrs[0].val.clusterDim.x = CLU;
    attrs[0].val.clusterDim.y = 1;
    attrs[0].val.clusterDim.z = 1;
    cfg.attrs = attrs;
    cfg.numAttrs = 1;
    cudaLaunchKernelEx(&cfg, lstm_fused, x, Wf, bf, Wi, bi, Wg, bg, Wo, bo, out);
}

// round 15
// speedup vs baseline: 2.4035x; 1.7906x over previous
#include <cuda_runtime.h>
#include <cstdint>

#define TT   1024
#define BSZ  64
#define G4   1024
#define TBH  (TT*BSZ*256)
#define BH   (BSZ*256)
#define NCTA 128             // 16 clusters x 8 CTAs
#define CLU  8
#define NTHR 512

typedef unsigned long long ull;

// Scratch (device globals: no runtime allocation allowed)
__device__ float g_Z[(size_t)TT * BSZ * G4];   // [t][b][gate*256+u]  (256 MB)
__device__ int   g_done[512];                  // per-y-tile completion counters

#define FMA_F32X2(d, a, b, c) \
    asm("fma.rn.f32x2 %0, %1, %2, %3;" : "=l"(d) : "l"(a), "l"(b), "l"(c))
#define ADD_F32X2(d, a, b) \
    asm("add.rn.f32x2 %0, %1, %2;" : "=l"(d) : "l"(a), "l"(b))
#define UNPACK2(lo, hi, s) \
    asm("mov.b64 {%0, %1}, %2;" : "=f"(lo), "=f"(hi) : "l"(s))

__global__ void reset_kernel() {
    g_done[threadIdx.x] = 0;
}

// ---------------------------------------------------------------------------
// Phase 1: Z[t][b][g*256+u] = bias_g[u] + sum_k x[t][b][k] * W_g[u*512 + k]
// GEMM M=65536, N=1024, K=256. BM=128, BN=128, BK=16, 8x8 tiles.
// Runs CONCURRENTLY with lstm on a second stream (free SMs). Each block
// signals completion of its y-tile via fence + atomicAdd(g_done[y]).
// ---------------------------------------------------------------------------
__global__ __launch_bounds__(256, 2)
void proj_kernel(const float* __restrict__ x,
                 const float* __restrict__ Wf, const float* __restrict__ bf,
                 const float* __restrict__ Wi, const float* __restrict__ bi,
                 const float* __restrict__ Wg, const float* __restrict__ bg,
                 const float* __restrict__ Wo, const float* __restrict__ bo)
{
    __shared__ float As[16 * 132];
    __shared__ float Bs[16 * 132];

    const int tid = threadIdx.x;
    const int tx  = tid & 15;
    const int ty  = tid >> 4;
    const int bm    = blockIdx.y * 128;
    const int gate  = blockIdx.x >> 1;
    const int ucol0 = (blockIdx.x & 1) * 128;

    const float* W    = (gate == 0) ? Wf : (gate == 1) ? Wi : (gate == 2) ? Wg : Wo;
    const float* bias = (gate == 0) ? bf : (gate == 1) ? bi : (gate == 2) ? bg : bo;

    float acc[8][8];
#pragma unroll
    for (int i = 0; i < 8; i++)
#pragma unroll
        for (int j = 0; j < 8; j++) acc[i][j] = 0.f;

    for (int k0 = 0; k0 < 256; k0 += 16) {
#pragma unroll
        for (int it = 0; it < 2; it++) {
            int f4  = tid + it * 256;
            int row = f4 >> 2;
            int kc  = (f4 & 3) << 2;
            float4 av = *(const float4*)(x + (size_t)(bm + row) * 256 + k0 + kc);
            As[(kc + 0) * 132 + row] = av.x;
            As[(kc + 1) * 132 + row] = av.y;
            As[(kc + 2) * 132 + row] = av.z;
            As[(kc + 3) * 132 + row] = av.w;
            float4 bv = *(const float4*)(W + (size_t)(ucol0 + row) * 512 + k0 + kc);
            Bs[(kc + 0) * 132 + row] = bv.x;
            Bs[(kc + 1) * 132 + row] = bv.y;
            Bs[(kc + 2) * 132 + row] = bv.z;
            Bs[(kc + 3) * 132 + row] = bv.w;
        }
        __syncthreads();
#pragma unroll
        for (int kk = 0; kk < 16; kk++) {
            float4 a0 = *(const float4*)&As[kk * 132 + ty * 8];
            float4 a1 = *(const float4*)&As[kk * 132 + ty * 8 + 4];
            float4 b0 = *(const float4*)&Bs[kk * 132 + tx * 8];
            float4 b1 = *(const float4*)&Bs[kk * 132 + tx * 8 + 4];
            float a[8] = {a0.x, a0.y, a0.z, a0.w, a1.x, a1.y, a1.z, a1.w};
            float b[8] = {b0.x, b0.y, b0.z, b0.w, b1.x, b1.y, b1.z, b1.w};
#pragma unroll
            for (int i = 0; i < 8; i++)
#pragma unroll
                for (int j = 0; j < 8; j++) acc[i][j] += a[i] * b[j];
        }
        __syncthreads();
    }

    float4 q0 = *(const float4*)(bias + ucol0 + tx * 8);
    float4 q1 = *(const float4*)(bias + ucol0 + tx * 8 + 4);
    float bb[8] = {q0.x, q0.y, q0.z, q0.w, q1.x, q1.y, q1.z, q1.w};

#pragma unroll
    for (int i = 0; i < 8; i++) {
        size_t m  = (size_t)(bm + ty * 8 + i);
        float* zp = g_Z + m * 1024 + gate * 256 + ucol0 + tx * 8;
        float4 v0 = {acc[i][0] + bb[0], acc[i][1] + bb[1], acc[i][2] + bb[2], acc[i][3] + bb[3]};
        float4 v1 = {acc[i][4] + bb[4], acc[i][5] + bb[5], acc[i][6] + bb[6], acc[i][7] + bb[7]};
        *(float4*)zp       = v0;
        *(float4*)(zp + 4) = v1;
    }

    // publish: all stores of this block visible, then bump tile counter
    __threadfence();
    __syncthreads();
    if (tid == 0) atomicAdd(&g_done[blockIdx.y], 1);
}

// ---------------------------------------------------------------------------
// Phase 2: cluster-local recurrence (R8 champion config). 16 clusters x 8
// CTAs x 512 threads. Cluster cid owns batches [4cid,4cid+4); CTA rank r
// owns units [32r,32r+32) = 128 gate cols. h in per-CTA SMEM (dbl buffered),
// DSMEM pushes + one cluster barrier per step. Z reads are GUARDED on the
// proj progress counters (acquire load, cached per-thread).
// ---------------------------------------------------------------------------
__device__ __forceinline__ float sig_(float v)  { return __fdividef(1.f, 1.f + __expf(-v)); }
__device__ __forceinline__ float tanh_(float v) { return __fdividef(2.f, 1.f + __expf(-2.f * v)) - 1.f; }

__device__ __forceinline__ uint32_t smem_u32(const void* p) {
    uint32_t a;
    asm("{ .reg .u64 t; cvta.to.shared.u64 t, %1; cvt.u32.u64 %0, t; }"
        : "=r"(a) : "l"(p));
    return a;
}

__device__ __forceinline__ void push_h(uint32_t laddr, int rank, float v) {
    uint32_t ra;
    asm("mapa.shared::cluster.u32 %0, %1, %2;" : "=r"(ra) : "r"(laddr), "r"(rank));
    asm volatile("st.shared::cluster.f32 [%0], %1;" :: "r"(ra), "f"(v));
}

__device__ __forceinline__ int ld_acq(const int* p) {
    int v;
    asm volatile("ld.acquire.gpu.global.s32 %0, [%1];" : "=r"(v) : "l"(p) : "memory");
    return v;
}

#define CLUSTER_SYNC_() do { \
    asm volatile("barrier.cluster.arrive.aligned;" ::: "memory"); \
    asm volatile("barrier.cluster.wait.aligned;"   ::: "memory"); \
} while (0)

__global__ __launch_bounds__(NTHR, 1)
void lstm_kernel(const float* __restrict__ Wf, const float* __restrict__ Wi,
                 const float* __restrict__ Wg, const float* __restrict__ Wo,
                 float* __restrict__ out)
{
    __shared__ float hs[2][4][256];     // [buf][bq][k]  (8KB)
    __shared__ float pre4[4][4][128];   // [bq][kq][col] (8KB)

    const int tid  = threadIdx.x;
    const int lane = tid & 31;
    const int w    = tid >> 5;
    const int kq   = w >> 2;            // k-range [64kq, 64kq+64)
    const int cg   = w & 3;
    const int lc   = cg * 32 + lane;    // local col 0..127

    uint32_t rank;
    asm("mov.u32 %0, %%cluster_ctarank;" : "=r"(rank));
    const int cid = blockIdx.x >> 3;
    const int b0  = cid * 4;

    // ---- recurrent weights: this thread's col, k in [64kq, 64kq+64) ----
    const int uu = lc >> 2;
    const int gt = lc & 3;
    const float* Ws[4] = {Wf, Wi, Wg, Wo};
    const ull* wrow = (const ull*)(Ws[gt] + (size_t)(rank * 32 + uu) * 512 + 256 + kq * 64);
    ull wk[32];
#pragma unroll
    for (int j = 0; j < 32; j++) wk[j] = wrow[j];

    // zero h buffers
    for (int i = tid; i < 2 * 4 * 256; i += NTHR) ((float*)hs)[i] = 0.f;

    // epilogue identity (threads 0..127): bq = tid>>5, uue = tid&31
    const int bq_e  = tid >> 5;
    const int uu_e  = tid & 31;
    const int bg_e  = b0 + bq_e;
    const int ug_e  = (int)rank * 32 + uu_e;
    const uint32_t haddr0 = smem_u32(&hs[0][bq_e][ug_e]);
    const uint32_t haddr1 = smem_u32(&hs[1][bq_e][ug_e]);
    float cstate = 0.f;
    int have_y = -1;                    // proj progress cached per thread

    CLUSTER_SYNC_();   // hs zeros visible cluster-wide

    for (int t = 0; t < TT; t++) {
        // ---- guarded Z prefetch for this step ----
        float z0, z1, z2, z3;
        if (tid < 128) {
            const int yneed = t >> 1;
            if (yneed > have_y) {
                while (ld_acq(&g_done[yneed]) < 8) {}
                have_y = yneed;
            }
            const float* zr = g_Z + ((size_t)t * 64 + bg_e) * 1024 + ug_e;
            z0 = __ldcs(zr);
            z1 = __ldcs(zr + 256);
            z2 = __ldcs(zr + 512);
            z3 = __ldcs(zr + 768);
        }

        // ---- recurrent GEMM: 4 batches, this thread's col, 64 k's ----
        const int buf = t & 1;
#pragma unroll
        for (int bq = 0; bq < 4; bq++) {
            const ulonglong2* hp2 = (const ulonglong2*)&hs[buf][bq][kq * 64]; // 16 ull2
            ull a0 = 0ull, a1 = 0ull;
#pragma unroll
            for (int j = 0; j < 16; j++) {
                ulonglong2 hv = hp2[j];
                FMA_F32X2(a0, wk[2 * j + 0], hv.x, a0);
                FMA_F32X2(a1, wk[2 * j + 1], hv.y, a1);
            }
            ADD_F32X2(a0, a0, a1);
            float lo, hi; UNPACK2(lo, hi, a0);
            pre4[bq][kq][lc] = lo + hi;
        }
        __syncthreads();

        // ---- epilogue: 128 threads, one (batch, unit) each ----
        if (tid < 128) {
            float pf = 0.f, pi = 0.f, pg = 0.f, po = 0.f;
#pragma unroll
            for (int q = 0; q < 4; q++) {
                float4 s = *(const float4*)&pre4[bq_e][q][uu_e * 4];
                pf += s.x; pi += s.y; pg += s.z; po += s.w;
            }
            float fg = sig_ (pf + z0);
            float ig = sig_ (pi + z1);
            float gg = tanh_(pg + z2);
            float og = sig_ (po + z3);
            cstate = fg * cstate + ig * gg;
            float h = og * tanh_(cstate);

            uint32_t ha = (buf ? haddr0 : haddr1);
#pragma unroll
            for (int r = 0; r < CLU; r++) push_h(ha, r, h);

            out[((size_t)t * 64 + bg_e) * 256 + ug_e] = h;
            if (t == TT - 1) {
                out[TBH + bg_e * 256 + ug_e]      = h;
                out[TBH + BH + bg_e * 256 + ug_e] = cstate;
            }
        }

        CLUSTER_SYNC_();
    }
}

// ---------------------------------------------------------------------------
// Launch: reset -> fork (proj on s2 || lstm on capture stream) -> join.
// ---------------------------------------------------------------------------
extern "C" void kernel_launch(void* const* d_in, const int* in_sizes, int n_in,
                              void* d_out, int out_size)
{
    const float* x  = (const float*)d_in[0];
    const float* Wf = (const float*)d_in[1];
    const float* bf = (const float*)d_in[2];
    const float* Wi = (const float*)d_in[3];
    const float* bi = (const float*)d_in[4];
    const float* Wg = (const float*)d_in[5];
    const float* bg = (const float*)d_in[6];
    const float* Wo = (const float*)d_in[7];
    const float* bo = (const float*)d_in[8];
    float* out = (float*)d_out;

    static cudaStream_t s2;
    static cudaEvent_t  evA, evB;
    static bool init = false;
    if (!init) {
        cudaStreamCreateWithFlags(&s2, cudaStreamNonBlocking);
        cudaEventCreateWithFlags(&evA, cudaEventDisableTiming);
        cudaEventCreateWithFlags(&evB, cudaEventDisableTiming);
        init = true;
    }

    reset_kernel<<<1, 512>>>();

    cudaEventRecord(evA, 0);
    cudaStreamWaitEvent(s2, evA, 0);

    proj_kernel<<<dim3(8, 512), 256, 0, s2>>>(x, Wf, bf, Wi, bi, Wg, bg, Wo, bo);

    cudaLaunchConfig_t cfg = {};
    cfg.gridDim  = dim3(NCTA, 1, 1);
    cfg.blockDim = dim3(NTHR, 1, 1);
    cfg.dynamicSmemBytes = 0;
    cudaLaunchAttribute attrs[1];
    attrs[0].id = cudaLaunchAttributeClusterDimension;
    attrs[0].val.clusterDim.x = CLU;
    attrs[0].val.clusterDim.y = 1;
    attrs[0].val.clusterDim.z = 1;
    cfg.attrs = attrs;
    cfg.numAttrs = 1;
    cudaLaunchKernelEx(&cfg, lstm_kernel, Wf, Wi, Wg, Wo, out);

    cudaEventRecord(evB, s2);
    cudaStreamWaitEvent(0, evB, 0);
}

// round 16
// speedup vs baseline: 2.4739x; 1.0293x over previous
#include <cuda_runtime.h>
#include <cstdint>

#define TT   1024
#define BSZ  64
#define G4   1024
#define TBH  (TT*BSZ*256)
#define BH   (BSZ*256)
#define NCTA 128             // 16 clusters x 8 CTAs
#define CLU  8
#define NTHR 512

typedef unsigned long long ull;

// Scratch (device globals: no runtime allocation allowed)
__device__ float g_Z[(size_t)TT * BSZ * G4];   // [t][b][gate*256+u]  (256 MB)
__device__ int   g_done[512];                  // per-y-tile completion counters

#define FMA_F32X2(d, a, b, c) \
    asm("fma.rn.f32x2 %0, %1, %2, %3;" : "=l"(d) : "l"(a), "l"(b), "l"(c))
#define ADD_F32X2(d, a, b) \
    asm("add.rn.f32x2 %0, %1, %2;" : "=l"(d) : "l"(a), "l"(b))
#define UNPACK2(lo, hi, s) \
    asm("mov.b64 {%0, %1}, %2;" : "=f"(lo), "=f"(hi) : "l"(s))

__global__ void reset_kernel() {
    g_done[threadIdx.x] = 0;
}

// ---------------------------------------------------------------------------
// Phase 1: Z[t][b][g*256+u] = bias_g[u] + sum_k x[t][b][k] * W_g[u*512 + k]
// GEMM M=65536, N=1024, K=256. Runs CONCURRENTLY with lstm on stream s2
// (free SMs). Each block signals its y-tile via fence + atomicAdd.
// ---------------------------------------------------------------------------
__global__ __launch_bounds__(256, 2)
void proj_kernel(const float* __restrict__ x,
                 const float* __restrict__ Wf, const float* __restrict__ bf,
                 const float* __restrict__ Wi, const float* __restrict__ bi,
                 const float* __restrict__ Wg, const float* __restrict__ bg,
                 const float* __restrict__ Wo, const float* __restrict__ bo)
{
    __shared__ float As[16 * 132];
    __shared__ float Bs[16 * 132];

    const int tid = threadIdx.x;
    const int tx  = tid & 15;
    const int ty  = tid >> 4;
    const int bm    = blockIdx.y * 128;
    const int gate  = blockIdx.x >> 1;
    const int ucol0 = (blockIdx.x & 1) * 128;

    const float* W    = (gate == 0) ? Wf : (gate == 1) ? Wi : (gate == 2) ? Wg : Wo;
    const float* bias = (gate == 0) ? bf : (gate == 1) ? bi : (gate == 2) ? bg : bo;

    float acc[8][8];
#pragma unroll
    for (int i = 0; i < 8; i++)
#pragma unroll
        for (int j = 0; j < 8; j++) acc[i][j] = 0.f;

    for (int k0 = 0; k0 < 256; k0 += 16) {
#pragma unroll
        for (int it = 0; it < 2; it++) {
            int f4  = tid + it * 256;
            int row = f4 >> 2;
            int kc  = (f4 & 3) << 2;
            float4 av = *(const float4*)(x + (size_t)(bm + row) * 256 + k0 + kc);
            As[(kc + 0) * 132 + row] = av.x;
            As[(kc + 1) * 132 + row] = av.y;
            As[(kc + 2) * 132 + row] = av.z;
            As[(kc + 3) * 132 + row] = av.w;
            float4 bv = *(const float4*)(W + (size_t)(ucol0 + row) * 512 + k0 + kc);
            Bs[(kc + 0) * 132 + row] = bv.x;
            Bs[(kc + 1) * 132 + row] = bv.y;
            Bs[(kc + 2) * 132 + row] = bv.z;
            Bs[(kc + 3) * 132 + row] = bv.w;
        }
        __syncthreads();
#pragma unroll
        for (int kk = 0; kk < 16; kk++) {
            float4 a0 = *(const float4*)&As[kk * 132 + ty * 8];
            float4 a1 = *(const float4*)&As[kk * 132 + ty * 8 + 4];
            float4 b0 = *(const float4*)&Bs[kk * 132 + tx * 8];
            float4 b1 = *(const float4*)&Bs[kk * 132 + tx * 8 + 4];
            float a[8] = {a0.x, a0.y, a0.z, a0.w, a1.x, a1.y, a1.z, a1.w};
            float b[8] = {b0.x, b0.y, b0.z, b0.w, b1.x, b1.y, b1.z, b1.w};
#pragma unroll
            for (int i = 0; i < 8; i++)
#pragma unroll
                for (int j = 0; j < 8; j++) acc[i][j] += a[i] * b[j];
        }
        __syncthreads();
    }

    float4 q0 = *(const float4*)(bias + ucol0 + tx * 8);
    float4 q1 = *(const float4*)(bias + ucol0 + tx * 8 + 4);
    float bb[8] = {q0.x, q0.y, q0.z, q0.w, q1.x, q1.y, q1.z, q1.w};

#pragma unroll
    for (int i = 0; i < 8; i++) {
        size_t m  = (size_t)(bm + ty * 8 + i);
        float* zp = g_Z + m * 1024 + gate * 256 + ucol0 + tx * 8;
        float4 v0 = {acc[i][0] + bb[0], acc[i][1] + bb[1], acc[i][2] + bb[2], acc[i][3] + bb[3]};
        float4 v1 = {acc[i][4] + bb[4], acc[i][5] + bb[5], acc[i][6] + bb[6], acc[i][7] + bb[7]};
        *(float4*)zp       = v0;
        *(float4*)(zp + 4) = v1;
    }

    __threadfence();
    __syncthreads();
    if (tid == 0) atomicAdd(&g_done[blockIdx.y], 1);
}

// ---------------------------------------------------------------------------
// Phase 2: cluster recurrence with SOURCE-SPLIT barriers.
// 16 clusters x 8 CTAs x 512 threads. CTA rank r owns units [32r,32r+32).
// Two per-CTA mbarriers (count 4): mbarA <- ranks 0-3, mbarB <- ranks 4-7.
// Warps kq<2 (k=[0,128), data from ranks 0-3) wait only A; warps kq>=2 wait
// only B. A late CTA delays only half the GEMM; the other half overlaps its
// propagation. Arrives are parallel (threads 0..7, one dest each).
// ---------------------------------------------------------------------------
__device__ __forceinline__ float sig_(float v)  { return __fdividef(1.f, 1.f + __expf(-v)); }
__device__ __forceinline__ float tanh_(float v) { return __fdividef(2.f, 1.f + __expf(-2.f * v)) - 1.f; }

__device__ __forceinline__ uint32_t smem_u32(const void* p) {
    uint32_t a;
    asm("{ .reg .u64 t; cvta.to.shared.u64 t, %1; cvt.u32.u64 %0, t; }"
        : "=r"(a) : "l"(p));
    return a;
}

__device__ __forceinline__ void push_h(uint32_t laddr, int rank, float v) {
    uint32_t ra;
    asm("mapa.shared::cluster.u32 %0, %1, %2;" : "=r"(ra) : "r"(laddr), "r"(rank));
    asm volatile("st.shared::cluster.f32 [%0], %1;" :: "r"(ra), "f"(v));
}

__device__ __forceinline__ void remote_arrive(uint32_t bar_laddr, int rank) {
    asm volatile(
        "{ .reg .b32 ra;\n\t"
        "mapa.shared::cluster.u32 ra, %0, %1;\n\t"
        "mbarrier.arrive.release.cluster.shared::cluster.b64 _, [ra]; }"
        :: "r"(bar_laddr), "r"(rank) : "memory");
}

__device__ __forceinline__ void bar_wait(uint32_t bar_laddr, unsigned parity) {
    asm volatile(
        "{ .reg .pred P;\n\t"
        "W_%=:\n\t"
        "mbarrier.try_wait.parity.acquire.cluster.shared::cta.b64 P, [%0], %1, 0x989680;\n\t"
        "@!P bra W_%=;\n\t"
        "}"
        :: "r"(bar_laddr), "r"(parity) : "memory");
}

__device__ __forceinline__ int ld_acq(const int* p) {
    int v;
    asm volatile("ld.acquire.gpu.global.s32 %0, [%1];" : "=r"(v) : "l"(p) : "memory");
    return v;
}

#define CLUSTER_SYNC_() do { \
    asm volatile("barrier.cluster.arrive.aligned;" ::: "memory"); \
    asm volatile("barrier.cluster.wait.aligned;"   ::: "memory"); \
} while (0)

__global__ __launch_bounds__(NTHR, 1)
void lstm_kernel(const float* __restrict__ Wf, const float* __restrict__ Wi,
                 const float* __restrict__ Wg, const float* __restrict__ Wo,
                 float* __restrict__ out)
{
    __shared__ float hs[2][4][256];     // [buf][bq][k]  (8KB)
    __shared__ float pre4[4][4][128];   // [bq][kq][col] (8KB)
    __shared__ ull   mbar[2];           // A: ranks 0-3, B: ranks 4-7

    const int tid  = threadIdx.x;
    const int lane = tid & 31;
    const int w    = tid >> 5;
    const int kq   = w >> 2;            // k-range [64kq, 64kq+64)
    const int cg   = w & 3;
    const int lc   = cg * 32 + lane;    // local col 0..127

    uint32_t rank;
    asm("mov.u32 %0, %%cluster_ctarank;" : "=r"(rank));
    const int cid = blockIdx.x >> 3;
    const int b0  = cid * 4;
    const uint32_t mbA = smem_u32(&mbar[0]);
    const uint32_t mbB = smem_u32(&mbar[1]);
    const uint32_t mb_my = (rank < 4) ? mbA : mbB;   // barrier class I signal
    const uint32_t mb_wait = (kq < 2) ? mbA : mbB;   // barrier class I consume

    // ---- recurrent weights: this thread's col, k in [64kq, 64kq+64) ----
    const int uu = lc >> 2;
    const int gt = lc & 3;
    const float* Ws[4] = {Wf, Wi, Wg, Wo};
    const ull* wrow = (const ull*)(Ws[gt] + (size_t)(rank * 32 + uu) * 512 + 256 + kq * 64);
    ull wk[32];
#pragma unroll
    for (int j = 0; j < 32; j++) wk[j] = wrow[j];

    // zero h buffers; init split barriers (4 arrivals each)
    for (int i = tid; i < 2 * 4 * 256; i += NTHR) ((float*)hs)[i] = 0.f;
    if (tid == 0) {
        asm volatile("mbarrier.init.shared.b64 [%0], %1;" :: "r"(mbA), "r"(4) : "memory");
        asm volatile("mbarrier.init.shared.b64 [%0], %1;" :: "r"(mbB), "r"(4) : "memory");
    }

    // epilogue identity (threads 0..127): bq = tid>>5, uue = tid&31
    const int bq_e  = tid >> 5;
    const int uu_e  = tid & 31;
    const int bg_e  = b0 + bq_e;
    const int ug_e  = (int)rank * 32 + uu_e;
    const uint32_t haddr0 = smem_u32(&hs[0][bq_e][ug_e]);
    const uint32_t haddr1 = smem_u32(&hs[1][bq_e][ug_e]);
    float cstate = 0.f;
    int have_y = -1;                    // proj progress cached per thread

    CLUSTER_SYNC_();   // hs zeros + barrier init visible cluster-wide

    for (int t = 0; t < TT; t++) {
        // ---- guarded Z prefetch (proj runs concurrently) ----
        float z0, z1, z2, z3;
        if (tid < 128) {
            const int yneed = t >> 1;
            if (yneed > have_y) {
                while (ld_acq(&g_done[yneed]) < 8) {}
                have_y = yneed;
            }
            const float* zr = g_Z + ((size_t)t * 64 + bg_e) * 1024 + ug_e;
            z0 = __ldcs(zr);
            z1 = __ldcs(zr + 256);
            z2 = __ldcs(zr + 512);
            z3 = __ldcs(zr + 768);
        }

        // ---- wait ONLY for the source half this warp consumes ----
        if (t > 0) bar_wait(mb_wait, (unsigned)((t - 1) & 1));

        // ---- recurrent GEMM: 4 batches, this thread's col, 64 k's ----
        const int buf = t & 1;
#pragma unroll
        for (int bq = 0; bq < 4; bq++) {
            const ulonglong2* hp2 = (const ulonglong2*)&hs[buf][bq][kq * 64]; // 16 ull2
            ull a0 = 0ull, a1 = 0ull;
#pragma unroll
            for (int j = 0; j < 16; j++) {
                ulonglong2 hv = hp2[j];
                FMA_F32X2(a0, wk[2 * j + 0], hv.x, a0);
                FMA_F32X2(a1, wk[2 * j + 1], hv.y, a1);
            }
            ADD_F32X2(a0, a0, a1);
            float lo, hi; UNPACK2(lo, hi, a0);
            pre4[bq][kq][lc] = lo + hi;
        }
        __syncthreads();

        // ---- epilogue: 128 threads, one (batch, unit) each ----
        if (tid < 128) {
            float pf = 0.f, pi = 0.f, pg = 0.f, po = 0.f;
#pragma unroll
            for (int q = 0; q < 4; q++) {
                float4 s = *(const float4*)&pre4[bq_e][q][uu_e * 4];
                pf += s.x; pi += s.y; pg += s.z; po += s.w;
            }
            float fg = sig_ (pf + z0);
            float ig = sig_ (pi + z1);
            float gg = tanh_(pg + z2);
            float og = sig_ (po + z3);
            cstate = fg * cstate + ig * gg;
            float h = og * tanh_(cstate);

            uint32_t ha = (buf ? haddr0 : haddr1);
#pragma unroll
            for (int r = 0; r < CLU; r++) push_h(ha, r, h);

            out[((size_t)t * 64 + bg_e) * 256 + ug_e] = h;
            if (t == TT - 1) {
                out[TBH + bg_e * 256 + ug_e]      = h;
                out[TBH + BH + bg_e * 256 + ug_e] = cstate;
            }
        }

        // pushes (warps 0-3) ordered before arrives via syncthreads;
        // threads 0..7 release-arrive in PARALLEL, one dest CTA each.
        __syncthreads();
        if (tid < CLU) remote_arrive(mb_my, tid);
    }

    // no CTA exits while peers may still push/arrive into its SMEM
    CLUSTER_SYNC_();
}

// ---------------------------------------------------------------------------
// Launch: reset -> fork (proj on s2 || lstm on capture stream) -> join.
// ---------------------------------------------------------------------------
extern "C" void kernel_launch(void* const* d_in, const int* in_sizes, int n_in,
                              void* d_out, int out_size)
{
    const float* x  = (const float*)d_in[0];
    const float* Wf = (const float*)d_in[1];
    const float* bf = (const float*)d_in[2];
    const float* Wi = (const float*)d_in[3];
    const float* bi = (const float*)d_in[4];
    const float* Wg = (const float*)d_in[5];
    const float* bg = (const float*)d_in[6];
    const float* Wo = (const float*)d_in[7];
    const float* bo = (const float*)d_in[8];
    float* out = (float*)d_out;

    static cudaStream_t s2;
    static cudaEvent_t  evA, evB;
    static bool init = false;
    if (!init) {
        cudaStreamCreateWithFlags(&s2, cudaStreamNonBlocking);
        cudaEventCreateWithFlags(&evA, cudaEventDisableTiming);
        cudaEventCreateWithFlags(&evB, cudaEventDisableTiming);
        init = true;
    }

    reset_kernel<<<1, 512>>>();

    cudaEventRecord(evA, 0);
    cudaStreamWaitEvent(s2, evA, 0);

    proj_kernel<<<dim3(8, 512), 256, 0, s2>>>(x, Wf, bf, Wi, bi, Wg, bg, Wo, bo);

    cudaLaunchConfig_t cfg = {};
    cfg.gridDim  = dim3(NCTA, 1, 1);
    cfg.blockDim = dim3(NTHR, 1, 1);
    cfg.dynamicSmemBytes = 0;
    cudaLaunchAttribute attrs[1];
    attrs[0].id = cudaLaunchAttributeClusterDimension;
    attrs[0].val.clusterDim.x = CLU;
    attrs[0].val.clusterDim.y = 1;
    attrs[0].val.clusterDim.z = 1;
    cfg.attrs = attrs;
    cfg.numAttrs = 1;
    cudaLaunchKernelEx(&cfg, lstm_kernel, Wf, Wi, Wg, Wo, out);

    cudaEventRecord(evB, s2);
    cudaStreamWaitEvent(0, evB, 0);
}